// round 14
// baseline (speedup 1.0000x reference)
#include <cuda_runtime.h>
#include <cuda_fp16.h>
#include <cstdint>

#define BSZ   128
#define HID   1024
#define TSEQ  372
#define NCTA  128
#define NKT16 66
#define SB_U32 (NKT16 * 4 * 32 * 4)     // 33792 u32 = 135168 B

__device__ uint32_t g_hh[2][65536];      // h hi fragments (fp16x2)
__device__ uint32_t g_hl[2][65536];      // h lo*2048 fragments
__device__ uint32_t g_xh[TSEQ * 2048];   // x hi fragments (2 ktiles, k 0..31)
__device__ uint32_t g_xl[TSEQ * 2048];   // x lo*2048 fragments
__device__ float    g_bias[4096 * BSZ];
__device__ float    g_temb[HID * BSZ];
__device__ float    g_hm[512 * BSZ];
__device__ float    g_part[NCTA * 8 * BSZ];
__device__ unsigned g_cnt8[8 * 32];      // 8 counters, 128B apart

__device__ __forceinline__ float sigm(float x) { return 1.f / (1.f + expf(-x)); }

// pack two f32 -> f16x2, loE in LOW half
__device__ __forceinline__ uint32_t pk_h2(float loE, float hiE) {
    uint32_t r;
    asm("cvt.rn.f16x2.f32 %0, %1, %2;" : "=r"(r) : "f"(hiE), "f"(loE));
    return r;
}
__device__ __forceinline__ void split16(float v, float& hi, float& lo) {
    __half h = __float2half_rn(v);
    hi = __half2float(h);
    lo = (v - hi) * 2048.0f;
}
__device__ __forceinline__ void mma16816(float& d0, float& d1, float& d2, float& d3,
                                         uint32_t a0, uint32_t a1, uint32_t a2, uint32_t a3,
                                         uint32_t b0, uint32_t b1) {
    asm("mma.sync.aligned.m16n8k16.row.col.f32.f16.f16.f32 "
        "{%0,%1,%2,%3}, {%4,%5,%6,%7}, {%8,%9}, {%0,%1,%2,%3};"
        : "+f"(d0), "+f"(d1), "+f"(d2), "+f"(d3)
        : "r"(a0), "r"(a1), "r"(a2), "r"(a3), "r"(b0), "r"(b1));
}

// ---------------- setup ----------------
__global__ void s_emb_hm(const float* __restrict__ tval, const float* __restrict__ freqs,
                         const float* __restrict__ phases, const float* __restrict__ W1,
                         const float* __restrict__ b1)
{
    __shared__ float emb[256];
    const int b = blockIdx.x, tid = threadIdx.x;
    const float tv = tval[b];
    emb[tid] = cosf(fmaf(tv, freqs[tid], phases[tid])) * 1.41421356237309515f;
    __syncthreads();
    const float4* e4 = (const float4*)emb;
    for (int u = tid; u < 512; u += 256) {
        const float4* w4 = (const float4*)(W1 + u * 256);
        float s = b1[u];
        #pragma unroll 8
        for (int q = 0; q < 64; ++q) {
            float4 w = w4[q], e = e4[q];
            s += w.x * e.x + w.y * e.y + w.z * e.z + w.w * e.w;
        }
        g_hm[u * BSZ + b] = s * sigm(s);
    }
}

__global__ void s_temb(const float* __restrict__ W2, const float* __restrict__ b2)
{
    __shared__ float sW2[8 * 512];
    const int blk = blockIdx.x, tid = threadIdx.x;
    const int h0 = blk * 8;
    for (int idx = tid; idx < 4096; idx += 128) sW2[idx] = W2[h0 * 512 + idx];
    __syncthreads();
    const int b = tid;
    float acc[8];
    #pragma unroll
    for (int r = 0; r < 8; ++r) acc[r] = b2[h0 + r];
    #pragma unroll 8
    for (int u = 0; u < 512; ++u) {
        const float hmv = g_hm[u * BSZ + b];
        #pragma unroll
        for (int r = 0; r < 8; ++r) acc[r] = fmaf(sW2[r * 512 + u], hmv, acc[r]);
    }
    #pragma unroll
    for (int r = 0; r < 8; ++r) g_temb[(h0 + r) * BSZ + b] = acc[r];
}

// merged bias + x-fragment kernel (blocks 0..31 = bias, 32..403 = xfrag)
__global__ void s_biasx(const float* __restrict__ static_attr, const float* __restrict__ W_ih,
                        const float* __restrict__ b_ih, const float* __restrict__ b_hh,
                        const float* __restrict__ x_past, const float* __restrict__ x_future,
                        const float* __restrict__ noisy)
{
    const int blk = blockIdx.x, tid = threadIdx.x;
    if (blk < 32) {
        __shared__ float sst[27 * 128];
        __shared__ float sw[128 * 27];
        const int r0 = blk * 128;
        for (int idx = tid; idx < 27 * 128; idx += 256) {
            const int k = idx >> 7, b = idx & 127;
            sst[idx] = static_attr[b * 27 + k];
        }
        for (int idx = tid; idx < 128 * 27; idx += 256) {
            const int rl = idx / 27, k = idx - rl * 27;
            sw[idx] = W_ih[(r0 + rl) * 60 + 33 + k];
        }
        __syncthreads();
        for (int o = tid; o < 128 * 128; o += 256) {
            const int rl = o >> 7, b = o & 127;
            const int r = r0 + rl;
            float s = b_ih[r] + b_hh[r];
            #pragma unroll
            for (int k = 0; k < 27; ++k) s = fmaf(sw[rl * 27 + k], sst[k * 128 + b], s);
            g_bias[r * BSZ + b] = s;
        }
        for (int i = tid; i < 2048; i += 256) {
            g_hh[0][blk * 2048 + i] = 0u;
            g_hl[0][blk * 2048 + i] = 0u;
        }
        if (blk == 0 && tid < 8 * 32) g_cnt8[tid] = 0u;
    } else {
        const int t = blk - 32;
        if (tid >= 128) return;
        const int b = tid;
        const int mt = b >> 4, r = b & 15;
        const int gp = r & 7, up = r >> 3;
        const float* src = (t < 365) ? (x_past + (b * 365 + t) * 32)
                                     : (x_future + (b * 7 + (t - 365)) * 32);
        float xv[32];
        const float4* s4 = (const float4*)src;
        #pragma unroll
        for (int q = 0; q < 8; ++q) {
            float4 v = s4[q];
            xv[q * 4 + 0] = v.x; xv[q * 4 + 1] = v.y;
            xv[q * 4 + 2] = v.z; xv[q * 4 + 3] = v.w;
        }
        uint32_t* xh = g_xh + t * 2048;
        uint32_t* xl = g_xl + t * 2048;
        #pragma unroll
        for (int kt = 0; kt < 2; ++kt) {
            #pragma unroll
            for (int tg = 0; tg < 4; ++tg) {
                const int base = ((kt * 8 + mt) * 32 + gp * 4 + tg) * 4;
                #pragma unroll
                for (int hk = 0; hk < 2; ++hk) {
                    const int k0 = kt * 16 + tg * 2 + hk * 8;
                    float h0, l0, h1, l1;
                    split16(xv[k0], h0, l0);
                    split16(xv[k0 + 1], h1, l1);
                    xh[base + up + hk * 2] = pk_h2(h0, h1);
                    xl[base + up + hk * 2] = pk_h2(l0, l1);
                }
            }
        }
    }
}

// ---------------- main LSTM (fp16-split mma.sync, 512 thr, K-split, x-first schedule) ----------------
__global__ void __launch_bounds__(512, 1)
lstm_main(const float* __restrict__ W_hh, const float* __restrict__ W_ih,
          const float* __restrict__ Wh, const float* __restrict__ noisy)
{
    extern __shared__ __align__(16) uint32_t sm[];
    uint32_t* sB   = sm;                      // [66][4][32][4] u32
    float* bias_s  = (float*)(sm + SB_U32);   // 4096
    float* temb_s  = bias_s + 4096;           // 1024
    float* wh_s    = temb_s + 1024;           // 32 (8 used)
    float* red     = wh_s + 32;               // 256 * 18 floats

    const int tid = threadIdx.x;
    const int w   = tid >> 5, lane = tid & 31;
    const int wm  = w & 7, kg = w >> 3;
    const int g   = lane >> 2, tig = lane & 3;
    const int cta = blockIdx.x;
    const int j0  = cta * 8;

    // weights: kt 0..63 = W_hh, kt 64..65 = W_ih k 0..31 (flow column excluded)
    for (int idx = tid; idx < NKT16 * 4 * 32; idx += 512) {
        const int ln = idx & 31, nt = (idx >> 5) & 3, kt = idx >> 7;
        const int n = nt * 8 + (ln >> 2);
        const int tg = ln & 3;
        const int r = (n >> 3) * HID + j0 + (n & 7);
        const int k0 = kt * 16 + tg * 2;
        float wv[4];
        #pragma unroll
        for (int q = 0; q < 4; ++q) {
            const int k = k0 + (q >> 1) * 8 + (q & 1);
            float v = (k < 1024) ? W_hh[r * 1024 + k] : W_ih[r * 60 + (k - 1024)];
            wv[q] = v * 256.0f;
        }
        float h0, l0, h1, l1, h2, l2, h3, l3;
        split16(wv[0], h0, l0); split16(wv[1], h1, l1);
        split16(wv[2], h2, l2); split16(wv[3], h3, l3);
        uint32_t* dst = sB + idx * 4;
        dst[0] = pk_h2(h0, h1);
        dst[1] = pk_h2(h2, h3);
        dst[2] = pk_h2(l0, l1);
        dst[3] = pk_h2(l2, l3);
    }
    for (int idx = tid; idx < 32 * 128; idx += 512) {
        const int n = idx >> 7, b = idx & 127;
        bias_s[idx] = g_bias[((n >> 3) * HID + j0 + (n & 7)) * BSZ + b];
    }
    for (int idx = tid; idx < 8 * 128; idx += 512) {
        const int jl = idx >> 7, b = idx & 127;
        temb_s[idx] = g_temb[(j0 + jl) * BSZ + b];
    }
    if (tid < 8) wh_s[tid] = Wh[j0 + tid];
    __syncthreads();

    const int b_lo = wm * 16 + g;
    const int jl0 = 2 * tig, jl1 = jl0 + 1;
    const int ktw = cta >> 1;
    const int regw = (cta & 1) * 2;
    const int kt0h = kg * 32;                  // this group's h-tile base
    const int ktx = 64 + kg;                   // this group's x B-tile
    const int bb = kg ? (b_lo + 8) : b_lo;     // this group's batch row
    float* redp = red + (wm * 32 + lane) * 18;
    float cst[2] = {0.f, 0.f};

    const uint4* sB4 = (const uint4*)sB;

    // persistent across steps: ring slot 0 holds x-frag, Bc holds ktx block
    uint4 rh[2], rl[2], Bc[4];
    {
        const uint4* xh4 = (const uint4*)(g_xh);
        const uint4* xl4 = (const uint4*)(g_xl);
        const int xoff = (kg * 8 + wm) * 32 + lane;
        rh[0] = __ldcg(xh4 + xoff);
        rl[0] = __ldcg(xl4 + xoff);
        #pragma unroll
        for (int nt = 0; nt < 4; ++nt)
            Bc[nt] = sB4[(ktx * 4 + nt) * 32 + lane];
    }

    for (int t = 0; t < TSEQ; ++t) {
        const uint4* hh4 = (const uint4*)(g_hh[t & 1]);
        const uint4* hl4 = (const uint4*)(g_hl[t & 1]);

        float accM[4][4], accC[4][4];
        #pragma unroll
        for (int nt = 0; nt < 4; ++nt)
            #pragma unroll
            for (int e = 0; e < 4; ++e) { accM[nt][e] = 0.f; accC[nt][e] = 0.f; }

        // first h tile into slot 1
        {
            const int off = (kt0h * 8 + wm) * 32 + lane;
            rh[1] = __ldcg(hh4 + off);
            rl[1] = __ldcg(hl4 + off);
        }

        // schedule: k=0 -> x tile (ktx), k=1..32 -> h tiles kt0h..kt0h+31
        #pragma unroll 3
        for (int k = 0; k < 33; ++k) {
            const int cur = k & 1;
            const uint4 Ah = rh[cur], Al = rl[cur];
            // B prefetch: next k's tile; last iter reloads ktx for next step
            const int nb = (k < 32) ? (kt0h + k) : ktx;
            uint4 Bn[4];
            #pragma unroll
            for (int nt = 0; nt < 4; ++nt)
                Bn[nt] = sB4[(nb * 4 + nt) * 32 + lane];
            // A prefetch for k+2 (h tile kt0h + k + 1)
            if (k + 2 < 33) {
                const int off = ((kt0h + k + 1) * 8 + wm) * 32 + lane;
                rh[cur] = __ldcg(hh4 + off);
                rl[cur] = __ldcg(hl4 + off);
            }
            #pragma unroll
            for (int nt = 0; nt < 4; ++nt)
                mma16816(accM[nt][0], accM[nt][1], accM[nt][2], accM[nt][3],
                         Ah.x, Ah.y, Ah.z, Ah.w, Bc[nt].x, Bc[nt].y);
            #pragma unroll
            for (int nt = 0; nt < 4; ++nt)
                mma16816(accC[nt][0], accC[nt][1], accC[nt][2], accC[nt][3],
                         Al.x, Al.y, Al.z, Al.w, Bc[nt].x, Bc[nt].y);
            #pragma unroll
            for (int nt = 0; nt < 4; ++nt)
                mma16816(accC[nt][0], accC[nt][1], accC[nt][2], accC[nt][3],
                         Ah.x, Ah.y, Ah.z, Ah.w, Bc[nt].z, Bc[nt].w);
            #pragma unroll
            for (int nt = 0; nt < 4; ++nt) Bc[nt] = Bn[nt];
        }

        // combine hi/lo accumulators
        float part[4][4];
        #pragma unroll
        for (int nt = 0; nt < 4; ++nt)
            #pragma unroll
            for (int e = 0; e < 4; ++e)
                part[nt][e] = accM[nt][e] + accC[nt][e] * 4.8828125e-4f;

        // exchange: each group ships the half IT does not process
        if (kg == 0) {
            #pragma unroll
            for (int nt = 0; nt < 4; ++nt)
                *(float2*)(redp + 8 + nt * 2) = make_float2(part[nt][2], part[nt][3]);
        } else {
            #pragma unroll
            for (int nt = 0; nt < 4; ++nt)
                *(float2*)(redp + nt * 2) = make_float2(part[nt][0], part[nt][1]);
        }
        __syncthreads();

        // each group runs epilogue on its 2 accumulator slots
        const int eb = kg ? 2 : 0;
        const int ro = kg ? 8 : 0;
        float fl = 0.f;
        if (t >= 364) fl = __ldcg(noisy + bb * 8 + (t - 364));
        float hv[2];
        #pragma unroll
        for (int ee = 0; ee < 2; ++ee) {
            const int jl = ee ? jl1 : jl0;
            float gi = (part[0][eb + ee] + redp[ro + 0 * 2 + ee]) * 0.00390625f + bias_s[(0 + jl) * 128 + bb];
            float gf = (part[1][eb + ee] + redp[ro + 1 * 2 + ee]) * 0.00390625f + bias_s[(8 + jl) * 128 + bb];
            float gg = (part[2][eb + ee] + redp[ro + 2 * 2 + ee]) * 0.00390625f + bias_s[(16 + jl) * 128 + bb];
            float go = (part[3][eb + ee] + redp[ro + 3 * 2 + ee]) * 0.00390625f + bias_s[(24 + jl) * 128 + bb];
            if (t >= 364) {
                // exact fp32 flow (rank-1) term, active only in future steps
                gi += fl * __ldcg(W_ih + (j0 + jl) * 60 + 32);
                gf += fl * __ldcg(W_ih + (1024 + j0 + jl) * 60 + 32);
                gg += fl * __ldcg(W_ih + (2048 + j0 + jl) * 60 + 32);
                go += fl * __ldcg(W_ih + (3072 + j0 + jl) * 60 + 32);
            }
            cst[ee] = sigm(gf) * cst[ee] + sigm(gi) * tanhf(gg);
            float hn = sigm(go) * tanhf(cst[ee]);
            if (t == 363) {
                const float te = temb_s[jl * 128 + bb];
                hn += te; cst[ee] += te;
            }
            hv[ee] = hn;
        }

        // store h split into fragment layout for next step (kg0 -> slot regw, kg1 -> regw+1)
        {
            float h0, l0, h1, l1;
            split16(hv[0], h0, l0); split16(hv[1], h1, l1);
            const int addr = ((ktw * 8 + wm) * 32 + g * 4 + tig) * 4 + regw + kg;
            g_hh[(t + 1) & 1][addr] = pk_h2(h0, h1);
            g_hl[(t + 1) & 1][addr] = pk_h2(l0, l1);
        }

        if (t >= 364) {
            float p = hv[0] * wh_s[jl0] + hv[1] * wh_s[jl1];
            p += __shfl_xor_sync(0xFFFFFFFFu, p, 1);
            p += __shfl_xor_sync(0xFFFFFFFFu, p, 2);
            if (tig == 0)
                g_part[(cta * 8 + (t - 364)) * BSZ + bb] = p;
        }

        // prefetch next step's x fragments BEFORE the barrier (independent of h)
        {
            const int tn = (t + 1 < TSEQ) ? (t + 1) : t;
            const uint4* xh4 = (const uint4*)(g_xh + tn * 2048);
            const uint4* xl4 = (const uint4*)(g_xl + tn * 2048);
            const int xoff = (kg * 8 + wm) * 32 + lane;
            rh[0] = __ldcg(xh4 + xoff);
            rl[0] = __ldcg(xl4 + xoff);
        }

        // ---- grid barrier: release-arrive on 8 spread counters + acquire poll ----
        __syncthreads();
        if (tid == 0)
            asm volatile("red.release.gpu.global.add.u32 [%0], 1;"
                         :: "l"(g_cnt8 + (cta & 7) * 32) : "memory");
        if (tid < 8) {
            const unsigned target = 16u * (unsigned)(t + 1);
            unsigned v;
            do {
                asm volatile("ld.acquire.gpu.global.u32 %0, [%1];"
                             : "=r"(v) : "l"(g_cnt8 + tid * 32) : "memory");
                if (v < target) __nanosleep(32);
            } while (v < target);
        }
        __syncthreads();
    }
}

__global__ void out_kernel(const float* __restrict__ bh, float* __restrict__ out)
{
    const int idx = blockIdx.x * blockDim.x + threadIdx.x;
    if (idx >= BSZ * 8) return;
    const int b = idx >> 3, tf = idx & 7;
    float s = bh[0];
    #pragma unroll 4
    for (int c = 0; c < NCTA; ++c)
        s += g_part[(c * 8 + tf) * BSZ + b];
    out[idx] = s;
}

extern "C" void kernel_launch(void* const* d_in, const int* in_sizes, int n_in,
                              void* d_out, int out_size)
{
    const int smemb = SB_U32 * 4 + (4096 + 1024 + 32 + 256 * 18) * 4;
    cudaFuncSetAttribute(lstm_main, cudaFuncAttributeMaxDynamicSharedMemorySize, smemb);
    s_emb_hm<<<128, 256>>>((const float*)d_in[2], (const float*)d_in[9],
                           (const float*)d_in[10], (const float*)d_in[11],
                           (const float*)d_in[12]);
    s_temb<<<128, 128>>>((const float*)d_in[13], (const float*)d_in[14]);
    s_biasx<<<404, 256>>>((const float*)d_in[4], (const float*)d_in[5],
                          (const float*)d_in[7], (const float*)d_in[8],
                          (const float*)d_in[0], (const float*)d_in[3],
                          (const float*)d_in[1]);
    lstm_main<<<NCTA, 512, smemb>>>((const float*)d_in[6], (const float*)d_in[5],
                                    (const float*)d_in[15], (const float*)d_in[1]);
    out_kernel<<<(BSZ * 8 + 255) / 256, 256>>>((const float*)d_in[16], (float*)d_out);
}

// round 15
// speedup vs baseline: 1.5789x; 1.5789x over previous
#include <cuda_runtime.h>
#include <cuda_fp16.h>
#include <cstdint>

#define BSZ   128
#define HID   1024
#define TSEQ  372
#define NCTA  128
#define NKT16 66
#define SB_U32 (NKT16 * 4 * 32 * 4)     // 33792 u32 = 135168 B

__device__ uint32_t g_hh[2][65536];      // h hi fragments (fp16x2)
__device__ uint32_t g_hl[2][65536];      // h lo*2048 fragments
__device__ uint32_t g_xh[TSEQ * 2048];   // x hi fragments (2 ktiles, k 0..31)
__device__ uint32_t g_xl[TSEQ * 2048];   // x lo*2048 fragments
__device__ float    g_bias[4096 * BSZ];
__device__ float    g_temb[HID * BSZ];
__device__ float    g_hm[512 * BSZ];
__device__ float    g_part[NCTA * 8 * BSZ];
__device__ unsigned g_cnt8[8 * 32];      // 8 counters, 128B apart

__device__ __forceinline__ float sigm(float x) { return 1.f / (1.f + expf(-x)); }

// pack two f32 -> f16x2, loE in LOW half
__device__ __forceinline__ uint32_t pk_h2(float loE, float hiE) {
    uint32_t r;
    asm("cvt.rn.f16x2.f32 %0, %1, %2;" : "=r"(r) : "f"(hiE), "f"(loE));
    return r;
}
__device__ __forceinline__ void split16(float v, float& hi, float& lo) {
    __half h = __float2half_rn(v);
    hi = __half2float(h);
    lo = (v - hi) * 2048.0f;
}
__device__ __forceinline__ void mma16816(float& d0, float& d1, float& d2, float& d3,
                                         uint32_t a0, uint32_t a1, uint32_t a2, uint32_t a3,
                                         uint32_t b0, uint32_t b1) {
    asm("mma.sync.aligned.m16n8k16.row.col.f32.f16.f16.f32 "
        "{%0,%1,%2,%3}, {%4,%5,%6,%7}, {%8,%9}, {%0,%1,%2,%3};"
        : "+f"(d0), "+f"(d1), "+f"(d2), "+f"(d3)
        : "r"(a0), "r"(a1), "r"(a2), "r"(a3), "r"(b0), "r"(b1));
}

// ---------------- setup ----------------
__global__ void s_emb_hm(const float* __restrict__ tval, const float* __restrict__ freqs,
                         const float* __restrict__ phases, const float* __restrict__ W1,
                         const float* __restrict__ b1)
{
    __shared__ float emb[256];
    const int b = blockIdx.x, tid = threadIdx.x;
    const float tv = tval[b];
    emb[tid] = cosf(fmaf(tv, freqs[tid], phases[tid])) * 1.41421356237309515f;
    __syncthreads();
    const float4* e4 = (const float4*)emb;
    for (int u = tid; u < 512; u += 256) {
        const float4* w4 = (const float4*)(W1 + u * 256);
        float s = b1[u];
        #pragma unroll 8
        for (int q = 0; q < 64; ++q) {
            float4 w = w4[q], e = e4[q];
            s += w.x * e.x + w.y * e.y + w.z * e.z + w.w * e.w;
        }
        g_hm[u * BSZ + b] = s * sigm(s);
    }
}

__global__ void s_temb(const float* __restrict__ W2, const float* __restrict__ b2)
{
    __shared__ float sW2[8 * 512];
    const int blk = blockIdx.x, tid = threadIdx.x;
    const int h0 = blk * 8;
    for (int idx = tid; idx < 4096; idx += 128) sW2[idx] = W2[h0 * 512 + idx];
    __syncthreads();
    const int b = tid;
    float acc[8];
    #pragma unroll
    for (int r = 0; r < 8; ++r) acc[r] = b2[h0 + r];
    #pragma unroll 8
    for (int u = 0; u < 512; ++u) {
        const float hmv = g_hm[u * BSZ + b];
        #pragma unroll
        for (int r = 0; r < 8; ++r) acc[r] = fmaf(sW2[r * 512 + u], hmv, acc[r]);
    }
    #pragma unroll
    for (int r = 0; r < 8; ++r) g_temb[(h0 + r) * BSZ + b] = acc[r];
}

// merged bias + x-fragment kernel (blocks 0..31 = bias, 32..403 = xfrag)
__global__ void s_biasx(const float* __restrict__ static_attr, const float* __restrict__ W_ih,
                        const float* __restrict__ b_ih, const float* __restrict__ b_hh,
                        const float* __restrict__ x_past, const float* __restrict__ x_future,
                        const float* __restrict__ noisy)
{
    const int blk = blockIdx.x, tid = threadIdx.x;
    if (blk < 32) {
        __shared__ float sst[27 * 128];
        __shared__ float sw[128 * 27];
        const int r0 = blk * 128;
        for (int idx = tid; idx < 27 * 128; idx += 256) {
            const int k = idx >> 7, b = idx & 127;
            sst[idx] = static_attr[b * 27 + k];
        }
        for (int idx = tid; idx < 128 * 27; idx += 256) {
            const int rl = idx / 27, k = idx - rl * 27;
            sw[idx] = W_ih[(r0 + rl) * 60 + 33 + k];
        }
        __syncthreads();
        for (int o = tid; o < 128 * 128; o += 256) {
            const int rl = o >> 7, b = o & 127;
            const int r = r0 + rl;
            float s = b_ih[r] + b_hh[r];
            #pragma unroll
            for (int k = 0; k < 27; ++k) s = fmaf(sw[rl * 27 + k], sst[k * 128 + b], s);
            g_bias[r * BSZ + b] = s;
        }
        for (int i = tid; i < 2048; i += 256) {
            g_hh[0][blk * 2048 + i] = 0u;
            g_hl[0][blk * 2048 + i] = 0u;
        }
        if (blk == 0 && tid < 8 * 32) g_cnt8[tid] = 0u;
    } else {
        const int t = blk - 32;
        if (tid >= 128) return;
        const int b = tid;
        const int mt = b >> 4, r = b & 15;
        const int gp = r & 7, up = r >> 3;
        const float* src = (t < 365) ? (x_past + (b * 365 + t) * 32)
                                     : (x_future + (b * 7 + (t - 365)) * 32);
        float xv[32];
        const float4* s4 = (const float4*)src;
        #pragma unroll
        for (int q = 0; q < 8; ++q) {
            float4 v = s4[q];
            xv[q * 4 + 0] = v.x; xv[q * 4 + 1] = v.y;
            xv[q * 4 + 2] = v.z; xv[q * 4 + 3] = v.w;
        }
        uint32_t* xh = g_xh + t * 2048;
        uint32_t* xl = g_xl + t * 2048;
        #pragma unroll
        for (int kt = 0; kt < 2; ++kt) {
            #pragma unroll
            for (int tg = 0; tg < 4; ++tg) {
                const int base = ((kt * 8 + mt) * 32 + gp * 4 + tg) * 4;
                #pragma unroll
                for (int hk = 0; hk < 2; ++hk) {
                    const int k0 = kt * 16 + tg * 2 + hk * 8;
                    float h0, l0, h1, l1;
                    split16(xv[k0], h0, l0);
                    split16(xv[k0 + 1], h1, l1);
                    xh[base + up + hk * 2] = pk_h2(h0, h1);
                    xl[base + up + hk * 2] = pk_h2(l0, l1);
                }
            }
        }
    }
}

#define MMA_BLOCK(Ah_, Al_, B_)                                                   \
    _Pragma("unroll")                                                             \
    for (int nt = 0; nt < 4; ++nt)                                                \
        mma16816(accM[nt][0], accM[nt][1], accM[nt][2], accM[nt][3],              \
                 (Ah_).x, (Ah_).y, (Ah_).z, (Ah_).w, (B_)[nt].x, (B_)[nt].y);     \
    _Pragma("unroll")                                                             \
    for (int nt = 0; nt < 4; ++nt)                                                \
        mma16816(accC[nt][0], accC[nt][1], accC[nt][2], accC[nt][3],              \
                 (Al_).x, (Al_).y, (Al_).z, (Al_).w, (B_)[nt].x, (B_)[nt].y);     \
    _Pragma("unroll")                                                             \
    for (int nt = 0; nt < 4; ++nt)                                                \
        mma16816(accC[nt][0], accC[nt][1], accC[nt][2], accC[nt][3],              \
                 (Ah_).x, (Ah_).y, (Ah_).z, (Ah_).w, (B_)[nt].z, (B_)[nt].w);

// ---------------- main LSTM (fp16-split mma.sync, 512 thr, K-split, x-peeled) ----------------
__global__ void __launch_bounds__(512, 1)
lstm_main(const float* __restrict__ W_hh, const float* __restrict__ W_ih,
          const float* __restrict__ Wh, const float* __restrict__ noisy)
{
    extern __shared__ __align__(16) uint32_t sm[];
    uint32_t* sB   = sm;                      // [66][4][32][4] u32
    float* bias_s  = (float*)(sm + SB_U32);   // 4096
    float* temb_s  = bias_s + 4096;           // 1024
    float* wh_s    = temb_s + 1024;           // 32 (8 used)
    float* red     = wh_s + 32;               // 256 * 18 floats

    const int tid = threadIdx.x;
    const int w   = tid >> 5, lane = tid & 31;
    const int wm  = w & 7, kg = w >> 3;
    const int g   = lane >> 2, tig = lane & 3;
    const int cta = blockIdx.x;
    const int j0  = cta * 8;

    // weights: kt 0..63 = W_hh, kt 64..65 = W_ih k 0..31 (flow column excluded)
    for (int idx = tid; idx < NKT16 * 4 * 32; idx += 512) {
        const int ln = idx & 31, nt = (idx >> 5) & 3, kt = idx >> 7;
        const int n = nt * 8 + (ln >> 2);
        const int tg = ln & 3;
        const int r = (n >> 3) * HID + j0 + (n & 7);
        const int k0 = kt * 16 + tg * 2;
        float wv[4];
        #pragma unroll
        for (int q = 0; q < 4; ++q) {
            const int k = k0 + (q >> 1) * 8 + (q & 1);
            float v = (k < 1024) ? W_hh[r * 1024 + k] : W_ih[r * 60 + (k - 1024)];
            wv[q] = v * 256.0f;
        }
        float h0, l0, h1, l1, h2, l2, h3, l3;
        split16(wv[0], h0, l0); split16(wv[1], h1, l1);
        split16(wv[2], h2, l2); split16(wv[3], h3, l3);
        uint32_t* dst = sB + idx * 4;
        dst[0] = pk_h2(h0, h1);
        dst[1] = pk_h2(h2, h3);
        dst[2] = pk_h2(l0, l1);
        dst[3] = pk_h2(l2, l3);
    }
    for (int idx = tid; idx < 32 * 128; idx += 512) {
        const int n = idx >> 7, b = idx & 127;
        bias_s[idx] = g_bias[((n >> 3) * HID + j0 + (n & 7)) * BSZ + b];
    }
    for (int idx = tid; idx < 8 * 128; idx += 512) {
        const int jl = idx >> 7, b = idx & 127;
        temb_s[idx] = g_temb[(j0 + jl) * BSZ + b];
    }
    if (tid < 8) wh_s[tid] = Wh[j0 + tid];
    __syncthreads();

    const int b_lo = wm * 16 + g;
    const int jl0 = 2 * tig, jl1 = jl0 + 1;
    const int ktw = cta >> 1;
    const int regw = (cta & 1) * 2;
    const int kt0h = kg * 32;                  // this group's h-tile base
    const int ktx = 64 + kg;                   // this group's x B-tile
    const int bb = kg ? (b_lo + 8) : b_lo;     // this group's batch row
    float* redp = red + (wm * 32 + lane) * 18;
    float cst[2] = {0.f, 0.f};

    const uint4* sB4 = (const uint4*)sB;

    // persistent across steps: rh[0]/rl[0] hold next x-frag, Bc holds ktx block
    uint4 rh[2], rl[2], Bc[4];
    {
        const int xoff = (kg * 8 + wm) * 32 + lane;
        rh[0] = __ldcg((const uint4*)(g_xh) + xoff);
        rl[0] = __ldcg((const uint4*)(g_xl) + xoff);
        #pragma unroll
        for (int nt = 0; nt < 4; ++nt)
            Bc[nt] = sB4[(ktx * 4 + nt) * 32 + lane];
    }

    for (int t = 0; t < TSEQ; ++t) {
        const uint4* hh4 = (const uint4*)(g_hh[t & 1]);
        const uint4* hl4 = (const uint4*)(g_hl[t & 1]);

        float accM[4][4], accC[4][4];
        #pragma unroll
        for (int nt = 0; nt < 4; ++nt)
            #pragma unroll
            for (int e = 0; e < 4; ++e) { accM[nt][e] = 0.f; accC[nt][e] = 0.f; }

        // first h tile into slot 1
        {
            const int off = (kt0h * 8 + wm) * 32 + lane;
            rh[1] = __ldcg(hh4 + off);
            rl[1] = __ldcg(hl4 + off);
        }

        // ---- peeled x-tile iteration: A = rh[0] (x), B = Bc (ktx) ----
        {
            const uint4 Ah = rh[0], Al = rl[0];
            uint4 Bn[4];
            #pragma unroll
            for (int nt = 0; nt < 4; ++nt)
                Bn[nt] = sB4[(kt0h * 4 + nt) * 32 + lane];
            // prefetch h tile kt0h+1 into slot 0
            {
                const int off = ((kt0h + 1) * 8 + wm) * 32 + lane;
                rh[0] = __ldcg(hh4 + off);
                rl[0] = __ldcg(hl4 + off);
            }
            MMA_BLOCK(Ah, Al, Bc)
            #pragma unroll
            for (int nt = 0; nt < 4; ++nt) Bc[nt] = Bn[nt];
        }

        // ---- main loop: 32 h tiles; A slot = (k+1)&1 (compile-time, unroll 2) ----
        #pragma unroll 2
        for (int k = 0; k < 32; ++k) {
            const int cur = (k + 1) & 1;
            const uint4 Ah = rh[cur], Al = rl[cur];
            const int nb = (k < 31) ? (kt0h + k + 1) : ktx;
            uint4 Bn[4];
            #pragma unroll
            for (int nt = 0; nt < 4; ++nt)
                Bn[nt] = sB4[(nb * 4 + nt) * 32 + lane];
            if (k + 2 < 32) {
                const int off = ((kt0h + k + 2) * 8 + wm) * 32 + lane;
                rh[cur] = __ldcg(hh4 + off);
                rl[cur] = __ldcg(hl4 + off);
            }
            MMA_BLOCK(Ah, Al, Bc)
            #pragma unroll
            for (int nt = 0; nt < 4; ++nt) Bc[nt] = Bn[nt];
        }

        // combine hi/lo accumulators
        float part[4][4];
        #pragma unroll
        for (int nt = 0; nt < 4; ++nt)
            #pragma unroll
            for (int e = 0; e < 4; ++e)
                part[nt][e] = accM[nt][e] + accC[nt][e] * 4.8828125e-4f;

        // exchange: each group ships the half IT does not process
        if (kg == 0) {
            #pragma unroll
            for (int nt = 0; nt < 4; ++nt)
                *(float2*)(redp + 8 + nt * 2) = make_float2(part[nt][2], part[nt][3]);
        } else {
            #pragma unroll
            for (int nt = 0; nt < 4; ++nt)
                *(float2*)(redp + nt * 2) = make_float2(part[nt][0], part[nt][1]);
        }
        __syncthreads();

        // each group runs epilogue on its 2 accumulator slots
        const int eb = kg ? 2 : 0;
        const int ro = kg ? 8 : 0;
        float fl = 0.f;
        if (t >= 364) fl = __ldcg(noisy + bb * 8 + (t - 364));
        float hv[2];
        #pragma unroll
        for (int ee = 0; ee < 2; ++ee) {
            const int jl = ee ? jl1 : jl0;
            float gi = (part[0][eb + ee] + redp[ro + 0 * 2 + ee]) * 0.00390625f + bias_s[(0 + jl) * 128 + bb];
            float gf = (part[1][eb + ee] + redp[ro + 1 * 2 + ee]) * 0.00390625f + bias_s[(8 + jl) * 128 + bb];
            float gg = (part[2][eb + ee] + redp[ro + 2 * 2 + ee]) * 0.00390625f + bias_s[(16 + jl) * 128 + bb];
            float go = (part[3][eb + ee] + redp[ro + 3 * 2 + ee]) * 0.00390625f + bias_s[(24 + jl) * 128 + bb];
            if (t >= 364) {
                gi += fl * __ldcg(W_ih + (j0 + jl) * 60 + 32);
                gf += fl * __ldcg(W_ih + (1024 + j0 + jl) * 60 + 32);
                gg += fl * __ldcg(W_ih + (2048 + j0 + jl) * 60 + 32);
                go += fl * __ldcg(W_ih + (3072 + j0 + jl) * 60 + 32);
            }
            cst[ee] = sigm(gf) * cst[ee] + sigm(gi) * tanhf(gg);
            float hn = sigm(go) * tanhf(cst[ee]);
            if (t == 363) {
                const float te = temb_s[jl * 128 + bb];
                hn += te; cst[ee] += te;
            }
            hv[ee] = hn;
        }

        // store h split into fragment layout for next step (kg0 -> slot regw, kg1 -> regw+1)
        {
            float h0, l0, h1, l1;
            split16(hv[0], h0, l0); split16(hv[1], h1, l1);
            const int addr = ((ktw * 8 + wm) * 32 + g * 4 + tig) * 4 + regw + kg;
            g_hh[(t + 1) & 1][addr] = pk_h2(h0, h1);
            g_hl[(t + 1) & 1][addr] = pk_h2(l0, l1);
        }

        if (t >= 364) {
            float p = hv[0] * wh_s[jl0] + hv[1] * wh_s[jl1];
            p += __shfl_xor_sync(0xFFFFFFFFu, p, 1);
            p += __shfl_xor_sync(0xFFFFFFFFu, p, 2);
            if (tig == 0)
                g_part[(cta * 8 + (t - 364)) * BSZ + bb] = p;
        }

        // prefetch next step's x fragments BEFORE the barrier (independent of h)
        {
            const int tn = (t + 1 < TSEQ) ? (t + 1) : t;
            const int xoff = (kg * 8 + wm) * 32 + lane;
            rh[0] = __ldcg((const uint4*)(g_xh + tn * 2048) + xoff);
            rl[0] = __ldcg((const uint4*)(g_xl + tn * 2048) + xoff);
        }

        // ---- grid barrier: release-arrive on 8 spread counters + acquire poll ----
        __syncthreads();
        if (tid == 0)
            asm volatile("red.release.gpu.global.add.u32 [%0], 1;"
                         :: "l"(g_cnt8 + (cta & 7) * 32) : "memory");
        if (tid < 8) {
            const unsigned target = 16u * (unsigned)(t + 1);
            unsigned v;
            do {
                asm volatile("ld.acquire.gpu.global.u32 %0, [%1];"
                             : "=r"(v) : "l"(g_cnt8 + tid * 32) : "memory");
                if (v < target) __nanosleep(32);
            } while (v < target);
        }
        __syncthreads();
    }
}

__global__ void out_kernel(const float* __restrict__ bh, float* __restrict__ out)
{
    const int idx = blockIdx.x * blockDim.x + threadIdx.x;
    if (idx >= BSZ * 8) return;
    const int b = idx >> 3, tf = idx & 7;
    float s = bh[0];
    #pragma unroll 4
    for (int c = 0; c < NCTA; ++c)
        s += g_part[(c * 8 + tf) * BSZ + b];
    out[idx] = s;
}

extern "C" void kernel_launch(void* const* d_in, const int* in_sizes, int n_in,
                              void* d_out, int out_size)
{
    const int smemb = SB_U32 * 4 + (4096 + 1024 + 32 + 256 * 18) * 4;
    cudaFuncSetAttribute(lstm_main, cudaFuncAttributeMaxDynamicSharedMemorySize, smemb);
    s_emb_hm<<<128, 256>>>((const float*)d_in[2], (const float*)d_in[9],
                           (const float*)d_in[10], (const float*)d_in[11],
                           (const float*)d_in[12]);
    s_temb<<<128, 128>>>((const float*)d_in[13], (const float*)d_in[14]);
    s_biasx<<<404, 256>>>((const float*)d_in[4], (const float*)d_in[5],
                          (const float*)d_in[7], (const float*)d_in[8],
                          (const float*)d_in[0], (const float*)d_in[3],
                          (const float*)d_in[1]);
    lstm_main<<<NCTA, 512, smemb>>>((const float*)d_in[6], (const float*)d_in[5],
                                    (const float*)d_in[15], (const float*)d_in[1]);
    out_kernel<<<(BSZ * 8 + 255) / 256, 256>>>((const float*)d_in[16], (float*)d_out);
}